// round 12
// baseline (speedup 1.0000x reference)
#include <cuda_runtime.h>
#include <cuda_bf16.h>
#include <cstdint>
#include <math.h>

#define MAXN 100000
#define PAD 64

// ---- static scratch ----
__device__ __nv_bfloat16 g_hw0[MAXN * 128];  // messages layer 0 (bf16)
__device__ __nv_bfloat16 g_h1 [MAXN * 128];  // relu(agg0 + b0), bf16
__device__ __nv_bfloat16 g_hw1[MAXN * 64];   // messages layer 1 (bf16)
__device__ float g_dinv[MAXN];
__device__ int   g_cnt [MAXN];
__device__ int   g_col [MAXN * PAD];
__device__ float g_p[MAXN];
__device__ float g_q[MAXN];

__device__ __forceinline__ uint32_t pack_bf16x2(float lo, float hi) {
    __nv_bfloat162 h = __floats2bfloat162_rn(lo, hi);
    return *reinterpret_cast<uint32_t*>(&h);
}

__device__ __forceinline__ void mma_bf16(float c[4], const uint32_t a[4], const uint32_t b[2]) {
    asm volatile(
        "mma.sync.aligned.m16n8k16.row.col.f32.bf16.bf16.f32 "
        "{%0,%1,%2,%3}, {%4,%5,%6,%7}, {%8,%9}, {%0,%1,%2,%3};"
        : "+f"(c[0]), "+f"(c[1]), "+f"(c[2]), "+f"(c[3])
        : "r"(a[0]), "r"(a[1]), "r"(a[2]), "r"(a[3]), "r"(b[0]), "r"(b[1]));
}

// ================= padded adjacency build =================
__global__ void k_zero(int n) {
    int i = blockIdx.x * blockDim.x + threadIdx.x;
    if (i < n) g_cnt[i] = 0;
}

__global__ void k_fill(const int* __restrict__ ei, int E) {
    int e = blockIdx.x * blockDim.x + threadIdx.x;
    if (e >= E) return;
    int s = ei[e];
    int d = ei[E + e];
    int pos = atomicAdd(&g_cnt[d], 1);
    g_col[d * PAD + pos] = s;
}

__global__ void k_dinv(int n) {
    int i = blockIdx.x * blockDim.x + threadIdx.x;
    if (i < n) g_dinv[i] = rsqrtf((float)(g_cnt[i] + 1));
}

// ===== fully-tensor fused encoder + GEMM0 =====
#define EG0_XA 0
#define EG0_WB (EG0_XA + 8 * 136)
#define EG0_BE (EG0_WB + 8 * 136)
#define EG0_AS (EG0_BE + 128)
#define EG0_BS (EG0_AS + 64 * 136)
#define EG0_WORDS (EG0_BS + 64 * 136)

__global__ __launch_bounds__(256) void k_enc_gemm0(
    const float* __restrict__ x, const float* __restrict__ Wenc,
    const float* __restrict__ benc, const float* __restrict__ Wg0,
    __nv_bfloat16* __restrict__ C, int nRows) {
    extern __shared__ uint32_t sm[];
    uint32_t* xa = sm + EG0_XA;
    uint32_t* wb = sm + EG0_WB;
    float*    be = (float*)(sm + EG0_BE);
    uint32_t* As = sm + EG0_AS;
    uint32_t* Bs = sm + EG0_BS;

    int tid = threadIdx.x;
    int lane = tid & 31;
    int wid = tid >> 5;
    int g = lane >> 2, t = lane & 3;
    int wr = wid & 3;
    int wc = wid >> 2;
    int rowBase = blockIdx.x * 128;

    {
        int r = tid >> 1, q = tid & 1;
        int gr = rowBase + r;
        float4 v0 = make_float4(0.f, 0.f, 0.f, 0.f), v1 = v0;
        if (gr < nRows) {
            v0 = *(const float4*)(x + (size_t)gr * 16 + q * 8);
            v1 = *(const float4*)(x + (size_t)gr * 16 + q * 8 + 4);
        }
        xa[(q * 4 + 0) * 136 + r] = pack_bf16x2(v0.x, v0.y);
        xa[(q * 4 + 1) * 136 + r] = pack_bf16x2(v0.z, v0.w);
        xa[(q * 4 + 2) * 136 + r] = pack_bf16x2(v1.x, v1.y);
        xa[(q * 4 + 3) * 136 + r] = pack_bf16x2(v1.z, v1.w);
    }
#pragma unroll
    for (int i = 0; i < 4; ++i) {
        int idx = tid + i * 256;
        int kp = idx >> 7, n = idx & 127;
        wb[kp * 136 + n] = pack_bf16x2(Wenc[(size_t)(2 * kp) * 128 + n],
                                       Wenc[(size_t)(2 * kp + 1) * 128 + n]);
    }
    if (tid < 128) be[tid] = benc[tid];
    __syncthreads();

    float acc[2][8][4];
#pragma unroll
    for (int ma = 0; ma < 2; ++ma)
#pragma unroll
        for (int na = 0; na < 8; ++na)
#pragma unroll
            for (int q = 0; q < 4; ++q) acc[ma][na][q] = 0.f;
    {
        uint32_t af[2][4];
#pragma unroll
        for (int ma = 0; ma < 2; ++ma) {
            int rr = wr * 32 + ma * 16 + g;
            af[ma][0] = xa[t * 136 + rr];
            af[ma][1] = xa[t * 136 + rr + 8];
            af[ma][2] = xa[(t + 4) * 136 + rr];
            af[ma][3] = xa[(t + 4) * 136 + rr + 8];
        }
#pragma unroll
        for (int na = 0; na < 8; ++na) {
            int n = wc * 64 + na * 8 + g;
            uint32_t bf[2];
            bf[0] = wb[t * 136 + n];
            bf[1] = wb[(t + 4) * 136 + n];
#pragma unroll
            for (int ma = 0; ma < 2; ++ma) mma_bf16(acc[ma][na], af[ma], bf);
        }
    }
#pragma unroll
    for (int ma = 0; ma < 2; ++ma) {
        int r0 = wr * 32 + ma * 16 + g;
#pragma unroll
        for (int na = 0; na < 8; ++na) {
            int c = wc * 64 + na * 8 + 2 * t;
            int kp = wc * 32 + na * 4 + t;
            float b0 = be[c], b1 = be[c + 1];
            As[kp * 136 + r0] =
                pack_bf16x2(fmaxf(acc[ma][na][0] + b0, 0.f), fmaxf(acc[ma][na][1] + b1, 0.f));
            As[kp * 136 + r0 + 8] =
                pack_bf16x2(fmaxf(acc[ma][na][2] + b0, 0.f), fmaxf(acc[ma][na][3] + b1, 0.f));
        }
    }
#pragma unroll
    for (int i = 0; i < 32; ++i) {
        int idx = tid + i * 256;
        int kp = idx >> 7, n = idx & 127;
        Bs[kp * 136 + n] = pack_bf16x2(Wg0[(size_t)(2 * kp) * 128 + n],
                                       Wg0[(size_t)(2 * kp + 1) * 128 + n]);
    }
    __syncthreads();

#pragma unroll
    for (int ma = 0; ma < 2; ++ma)
#pragma unroll
        for (int na = 0; na < 8; ++na)
#pragma unroll
            for (int q = 0; q < 4; ++q) acc[ma][na][q] = 0.f;

#pragma unroll
    for (int ks = 0; ks < 8; ++ks) {
        int kpb = ks * 8;
        uint32_t af[2][4];
#pragma unroll
        for (int ma = 0; ma < 2; ++ma) {
            int rr = wr * 32 + ma * 16 + g;
            af[ma][0] = As[(kpb + t) * 136 + rr];
            af[ma][1] = As[(kpb + t) * 136 + rr + 8];
            af[ma][2] = As[(kpb + t + 4) * 136 + rr];
            af[ma][3] = As[(kpb + t + 4) * 136 + rr + 8];
        }
#pragma unroll
        for (int na = 0; na < 8; ++na) {
            int n = wc * 64 + na * 8 + g;
            uint32_t bf[2];
            bf[0] = Bs[(kpb + t) * 136 + n];
            bf[1] = Bs[(kpb + t + 4) * 136 + n];
#pragma unroll
            for (int ma = 0; ma < 2; ++ma) mma_bf16(acc[ma][na], af[ma], bf);
        }
    }
#pragma unroll
    for (int ma = 0; ma < 2; ++ma) {
        int r0 = rowBase + wr * 32 + ma * 16 + g;
#pragma unroll
        for (int na = 0; na < 8; ++na) {
            int col = wc * 64 + na * 8 + 2 * t;
            if (r0 < nRows)
                *(uint32_t*)(C + (size_t)r0 * 128 + col) = pack_bf16x2(acc[ma][na][0], acc[ma][na][1]);
            if (r0 + 8 < nRows)
                *(uint32_t*)(C + (size_t)(r0 + 8) * 128 + col) = pack_bf16x2(acc[ma][na][2], acc[ma][na][3]);
        }
    }
}

// ============ bf16 GEMM1 (A already bf16): hw1 = bf16(h1 @ W_g1) ============
#define G64_AS 0
#define G64_BS (G64_AS + 64 * 136)
#define G64_WORDS (G64_BS + 64 * 72)

__global__ __launch_bounds__(256) void k_gemm64(
    const __nv_bfloat16* __restrict__ A, const float* __restrict__ W,
    __nv_bfloat16* __restrict__ C, int nRows) {
    extern __shared__ uint32_t sm[];
    uint32_t* As = sm + G64_AS;
    uint32_t* Bs = sm + G64_BS;

    int tid = threadIdx.x;
    int lane = tid & 31;
    int wid = tid >> 5;
    int g = lane >> 2, t = lane & 3;
    int wr = wid & 3;
    int wc = wid >> 2;
    int rowBase = blockIdx.x * 128;

    const uint32_t* Aw = (const uint32_t*)(A + (size_t)rowBase * 128);
    int rowsHere = nRows - rowBase; if (rowsHere > 128) rowsHere = 128;
#pragma unroll
    for (int i = 0; i < 32; ++i) {
        int idx = tid + i * 256;
        int rr = idx >> 6;
        int kp = idx & 63;
        uint32_t v = 0;
        if (rr < rowsHere) v = Aw[idx];
        As[kp * 136 + rr] = v;
    }
#pragma unroll
    for (int i = 0; i < 16; ++i) {
        int idx = tid + i * 256;
        int kp = idx >> 6;
        int n = idx & 63;
        Bs[kp * 72 + n] = pack_bf16x2(W[(size_t)(2 * kp) * 64 + n],
                                      W[(size_t)(2 * kp + 1) * 64 + n]);
    }
    __syncthreads();

    float acc[2][4][4];
#pragma unroll
    for (int ma = 0; ma < 2; ++ma)
#pragma unroll
        for (int na = 0; na < 4; ++na)
#pragma unroll
            for (int q = 0; q < 4; ++q) acc[ma][na][q] = 0.f;

#pragma unroll
    for (int ks = 0; ks < 8; ++ks) {
        int kpb = ks * 8;
        uint32_t af[2][4];
#pragma unroll
        for (int ma = 0; ma < 2; ++ma) {
            int rr = wr * 32 + ma * 16 + g;
            af[ma][0] = As[(kpb + t) * 136 + rr];
            af[ma][1] = As[(kpb + t) * 136 + rr + 8];
            af[ma][2] = As[(kpb + t + 4) * 136 + rr];
            af[ma][3] = As[(kpb + t + 4) * 136 + rr + 8];
        }
#pragma unroll
        for (int na = 0; na < 4; ++na) {
            int n = wc * 32 + na * 8 + g;
            uint32_t bf[2];
            bf[0] = Bs[(kpb + t) * 72 + n];
            bf[1] = Bs[(kpb + t + 4) * 72 + n];
#pragma unroll
            for (int ma = 0; ma < 2; ++ma) mma_bf16(acc[ma][na], af[ma], bf);
        }
    }
#pragma unroll
    for (int ma = 0; ma < 2; ++ma) {
        int r0 = rowBase + wr * 32 + ma * 16 + g;
#pragma unroll
        for (int na = 0; na < 4; ++na) {
            int col = wc * 32 + na * 8 + 2 * t;
            if (r0 < nRows)
                *(uint32_t*)(C + (size_t)r0 * 64 + col) = pack_bf16x2(acc[ma][na][0], acc[ma][na][1]);
            if (r0 + 8 < nRows)
                *(uint32_t*)(C + (size_t)(r0 + 8) * 64 + col) = pack_bf16x2(acc[ma][na][2], acc[ma][na][3]);
        }
    }
}

#define GATHERH(J)                                                            \
    {                                                                         \
        int si = __shfl_sync(0xffffffffu, idx, (J));                          \
        float wv = __shfl_sync(0xffffffffu, dv, (J));                         \
        uint32_t u = __ldg((const uint32_t*)(hw + (size_t)si * 128) + wordOff); \
        float2 v = __bfloat1622float2(*reinterpret_cast<__nv_bfloat162*>(&u)); \
        acc.x += v.x * wv; acc.y += v.y * wv;                                 \
    }

// ============ gather aggregation, D=128, TWO warps per node -> h1 (bf16) ============
// warp pair (wid/2 = slot, wid&1 = half): each warp covers 64 dims (uint32/lane).
__global__ void k_agg128(const __nv_bfloat16* __restrict__ hw, const float* __restrict__ b,
                         __nv_bfloat16* __restrict__ outh, int nRows) {
    int wid = threadIdx.x >> 5;
    int n = blockIdx.x * 4 + (wid >> 1);
    if (n >= nRows) return;
    int half = wid & 1;
    int lane = threadIdx.x & 31;
    int wordOff = half * 32 + lane;   // uint32 index within the 64-word row

    float di = g_dinv[n];
    float2 acc;
    {
        uint32_t u = __ldg((const uint32_t*)(hw + (size_t)n * 128) + wordOff);
        acc = __bfloat1622float2(*reinterpret_cast<__nv_bfloat162*>(&u));
    }
    float s2 = di * di;
    acc.x *= s2; acc.y *= s2;

    int cnt = g_cnt[n];
    const int* colp = g_col + n * PAD;
    for (int j0 = 0; j0 < cnt; j0 += 32) {
        int c = cnt - j0; if (c > 32) c = 32;
        int idx = 0; float dv = 0.f;
        if (lane < c) { idx = __ldg(colp + j0 + lane); dv = g_dinv[idx] * di; }
        int jj = 0;
        for (; jj + 8 <= c; jj += 8) {
            GATHERH(jj + 0) GATHERH(jj + 1) GATHERH(jj + 2) GATHERH(jj + 3)
            GATHERH(jj + 4) GATHERH(jj + 5) GATHERH(jj + 6) GATHERH(jj + 7)
        }
        for (; jj < c; ++jj) { GATHERH(jj) }
    }
    int c2 = 2 * wordOff;
    float o0 = fmaxf(acc.x + b[c2], 0.f);
    float o1 = fmaxf(acc.y + b[c2 + 1], 0.f);
    ((uint32_t*)(outh + (size_t)n * 128))[wordOff] = pack_bf16x2(o0, o1);
}

#define GATHER64(J)                                                          \
    {                                                                        \
        int si = __shfl_sync(0xffffffffu, idx, (J));                         \
        float wv = __shfl_sync(0xffffffffu, dv, (J));                        \
        uint32_t u = ((const uint32_t*)(hw + (size_t)si * 64))[lane];        \
        float2 v = __bfloat1622float2(*reinterpret_cast<__nv_bfloat162*>(&u)); \
        acc.x += v.x * wv; acc.y += v.y * wv;                                \
    }

// ===== gather aggregation D=64 + fused node head =====
__global__ void k_agg64_head(const __nv_bfloat16* __restrict__ hw, const float* __restrict__ b,
                             const float* __restrict__ Wsw, const float* __restrict__ Wv,
                             const float* __restrict__ bv, float* __restrict__ out_v,
                             int nRows) {
    int n = blockIdx.x * (blockDim.x >> 5) + (threadIdx.x >> 5);
    if (n >= nRows) return;
    int lane = threadIdx.x & 31;
    float di = g_dinv[n];
    float2 acc;
    {
        uint32_t u = ((const uint32_t*)(hw + (size_t)n * 64))[lane];
        acc = __bfloat1622float2(*reinterpret_cast<__nv_bfloat162*>(&u));
    }
    float s2 = di * di;
    acc.x *= s2; acc.y *= s2;

    int cnt = g_cnt[n];
    const int* colp = g_col + n * PAD;
    for (int j0 = 0; j0 < cnt; j0 += 32) {
        int c = cnt - j0; if (c > 32) c = 32;
        int idx = 0; float dv = 0.f;
        if (lane < c) { idx = __ldg(colp + j0 + lane); dv = g_dinv[idx] * di; }
        int jj = 0;
        for (; jj + 8 <= c; jj += 8) {
            GATHER64(jj + 0) GATHER64(jj + 1) GATHER64(jj + 2) GATHER64(jj + 3)
            GATHER64(jj + 4) GATHER64(jj + 5) GATHER64(jj + 6) GATHER64(jj + 7)
        }
        for (; jj < c; ++jj) { GATHER64(jj) }
    }
    int c2 = 2 * lane;
    float a0 = fmaxf(acc.x + b[c2], 0.f);
    float a1 = fmaxf(acc.y + b[c2 + 1], 0.f);

    float pp = a0 * Wsw[c2] + a1 * Wsw[c2 + 1];
    float qq = a0 * Wsw[64 + c2] + a1 * Wsw[64 + c2 + 1];
    float vv = a0 * Wv[c2] + a1 * Wv[c2 + 1];
#pragma unroll
    for (int o = 16; o; o >>= 1) {
        pp += __shfl_xor_sync(0xffffffffu, pp, o);
        qq += __shfl_xor_sync(0xffffffffu, qq, o);
        vv += __shfl_xor_sync(0xffffffffu, vv, o);
    }
    if (lane == 0) {
        g_p[n] = pp;
        g_q[n] = qq;
        float vr = 1.f / (1.f + expf(-(vv + bv[0])));
        float v = 0.9f + 0.2f * vr;
        float vw = fminf(fmaxf(v * v, 0.81f), 1.21f);
        out_v[n] = sqrtf(vw);
    }
}

// ================= per-edge head =================
__global__ void k_edge(const int* __restrict__ ei, int E,
                       const float* __restrict__ bsw, float* __restrict__ out) {
    int e = blockIdx.x * blockDim.x + threadIdx.x;
    if (e >= E) return;
    int s = ei[e];
    int d = ei[E + e];
    float z = __ldg(&g_p[s]) + __ldg(&g_q[d]) + bsw[0];
    float y = 1.f / (1.f + expf(-z));
    out[e] = fminf(fmaxf(y, 0.f), 1.f);
}

extern "C" void kernel_launch(void* const* d_in, const int* in_sizes, int n_in,
                              void* d_out, int out_size) {
    const float* x     = (const float*)d_in[0];
    const int*   ei    = (const int*)d_in[1];
    const float* W_enc = (const float*)d_in[2];
    const float* b_enc = (const float*)d_in[3];
    const float* W_g0  = (const float*)d_in[4];
    const float* b_g0  = (const float*)d_in[5];
    const float* W_g1  = (const float*)d_in[6];
    const float* b_g1  = (const float*)d_in[7];
    const float* W_sw  = (const float*)d_in[8];
    const float* b_sw  = (const float*)d_in[9];
    const float* W_v   = (const float*)d_in[10];
    const float* b_v   = (const float*)d_in[11];
    float* out = (float*)d_out;

    const int N = in_sizes[0] / 16;
    const int E = in_sizes[1] / 2;

    __nv_bfloat16 *p_hw0, *p_h1, *p_hw1;
    cudaGetSymbolAddress((void**)&p_hw0, g_hw0);
    cudaGetSymbolAddress((void**)&p_h1, g_h1);
    cudaGetSymbolAddress((void**)&p_hw1, g_hw1);

    static cudaStream_t s_side = nullptr;
    static cudaEvent_t s_fork = nullptr, s_join = nullptr;
    if (s_side == nullptr) {
        cudaStreamCreateWithFlags(&s_side, cudaStreamNonBlocking);
        cudaEventCreateWithFlags(&s_fork, cudaEventDisableTiming);
        cudaEventCreateWithFlags(&s_join, cudaEventDisableTiming);
        cudaFuncSetAttribute(k_enc_gemm0, cudaFuncAttributeMaxDynamicSharedMemorySize,
                             EG0_WORDS * 4);
        cudaFuncSetAttribute(k_gemm64, cudaFuncAttributeMaxDynamicSharedMemorySize,
                             G64_WORDS * 4);
    }

    // ---- fork: adjacency build on side stream, encoder+GEMM0 on main ----
    cudaEventRecord(s_fork, 0);
    cudaStreamWaitEvent(s_side, s_fork, 0);

    k_zero<<<(N + 255) / 256, 256, 0, s_side>>>(N);
    k_fill<<<(E + 255) / 256, 256, 0, s_side>>>(ei, E);
    k_dinv<<<(N + 255) / 256, 256, 0, s_side>>>(N);
    cudaEventRecord(s_join, s_side);

    k_enc_gemm0<<<(N + 127) / 128, 256, EG0_WORDS * 4>>>(x, W_enc, b_enc, W_g0, p_hw0, N);

    // ---- join ----
    cudaStreamWaitEvent(0, s_join, 0);

    // ---- layer 0 aggregation (2 warps/node) ----
    k_agg128<<<(N + 3) / 4, 256>>>(p_hw0, b_g0, p_h1, N);

    // ---- layer 1 ----
    k_gemm64<<<(N + 127) / 128, 256, G64_WORDS * 4>>>(p_h1, W_g1, p_hw1, N);
    k_agg64_head<<<(N + 7) / 8, 256>>>(p_hw1, b_g1, W_sw, W_v, b_v, out + E, N);

    // ---- per-edge head ----
    k_edge<<<(E + 255) / 256, 256>>>(ei, E, b_sw, out);
}

// round 13
// speedup vs baseline: 1.0660x; 1.0660x over previous
#include <cuda_runtime.h>
#include <cuda_bf16.h>
#include <cstdint>
#include <math.h>

#define MAXN 100000
#define PAD 64

// ---- static scratch ----
__device__ __nv_bfloat16 g_hw0[MAXN * 128];  // messages layer 0 (bf16)
__device__ __nv_bfloat16 g_h1 [MAXN * 128];  // relu(agg0 + b0), bf16
__device__ __nv_bfloat16 g_hw1[MAXN * 64];   // messages layer 1 (bf16)
__device__ float g_dinv[MAXN];
__device__ int   g_cnt [MAXN];
__device__ int   g_col [MAXN * PAD];
__device__ float g_p[MAXN];
__device__ float g_q[MAXN];

__device__ __forceinline__ uint32_t pack_bf16x2(float lo, float hi) {
    __nv_bfloat162 h = __floats2bfloat162_rn(lo, hi);
    return *reinterpret_cast<uint32_t*>(&h);
}

__device__ __forceinline__ void mma_bf16(float c[4], const uint32_t a[4], const uint32_t b[2]) {
    asm volatile(
        "mma.sync.aligned.m16n8k16.row.col.f32.bf16.bf16.f32 "
        "{%0,%1,%2,%3}, {%4,%5,%6,%7}, {%8,%9}, {%0,%1,%2,%3};"
        : "+f"(c[0]), "+f"(c[1]), "+f"(c[2]), "+f"(c[3])
        : "r"(a[0]), "r"(a[1]), "r"(a[2]), "r"(a[3]), "r"(b[0]), "r"(b[1]));
}

// ================= padded adjacency build =================
__global__ void k_zero(int n) {
    int i = blockIdx.x * blockDim.x + threadIdx.x;
    if (i < n) g_cnt[i] = 0;
}

__global__ void k_fill(const int* __restrict__ ei, int E) {
    int e = blockIdx.x * blockDim.x + threadIdx.x;
    if (e >= E) return;
    int s = ei[e];
    int d = ei[E + e];
    int pos = atomicAdd(&g_cnt[d], 1);
    g_col[d * PAD + pos] = s;
}

__global__ void k_dinv(int n) {
    int i = blockIdx.x * blockDim.x + threadIdx.x;
    if (i < n) g_dinv[i] = rsqrtf((float)(g_cnt[i] + 1));
}

// ===== fully-tensor fused encoder + GEMM0 =====
#define EG0_XA 0
#define EG0_WB (EG0_XA + 8 * 136)
#define EG0_BE (EG0_WB + 8 * 136)
#define EG0_AS (EG0_BE + 128)
#define EG0_BS (EG0_AS + 64 * 136)
#define EG0_WORDS (EG0_BS + 64 * 136)

__global__ __launch_bounds__(256) void k_enc_gemm0(
    const float* __restrict__ x, const float* __restrict__ Wenc,
    const float* __restrict__ benc, const float* __restrict__ Wg0,
    __nv_bfloat16* __restrict__ C, int nRows) {
    extern __shared__ uint32_t sm[];
    uint32_t* xa = sm + EG0_XA;
    uint32_t* wb = sm + EG0_WB;
    float*    be = (float*)(sm + EG0_BE);
    uint32_t* As = sm + EG0_AS;
    uint32_t* Bs = sm + EG0_BS;

    int tid = threadIdx.x;
    int lane = tid & 31;
    int wid = tid >> 5;
    int g = lane >> 2, t = lane & 3;
    int wr = wid & 3;
    int wc = wid >> 2;
    int rowBase = blockIdx.x * 128;

    {
        int r = tid >> 1, q = tid & 1;
        int gr = rowBase + r;
        float4 v0 = make_float4(0.f, 0.f, 0.f, 0.f), v1 = v0;
        if (gr < nRows) {
            v0 = *(const float4*)(x + (size_t)gr * 16 + q * 8);
            v1 = *(const float4*)(x + (size_t)gr * 16 + q * 8 + 4);
        }
        xa[(q * 4 + 0) * 136 + r] = pack_bf16x2(v0.x, v0.y);
        xa[(q * 4 + 1) * 136 + r] = pack_bf16x2(v0.z, v0.w);
        xa[(q * 4 + 2) * 136 + r] = pack_bf16x2(v1.x, v1.y);
        xa[(q * 4 + 3) * 136 + r] = pack_bf16x2(v1.z, v1.w);
    }
#pragma unroll
    for (int i = 0; i < 4; ++i) {
        int idx = tid + i * 256;
        int kp = idx >> 7, n = idx & 127;
        wb[kp * 136 + n] = pack_bf16x2(Wenc[(size_t)(2 * kp) * 128 + n],
                                       Wenc[(size_t)(2 * kp + 1) * 128 + n]);
    }
    if (tid < 128) be[tid] = benc[tid];
    __syncthreads();

    float acc[2][8][4];
#pragma unroll
    for (int ma = 0; ma < 2; ++ma)
#pragma unroll
        for (int na = 0; na < 8; ++na)
#pragma unroll
            for (int q = 0; q < 4; ++q) acc[ma][na][q] = 0.f;
    {
        uint32_t af[2][4];
#pragma unroll
        for (int ma = 0; ma < 2; ++ma) {
            int rr = wr * 32 + ma * 16 + g;
            af[ma][0] = xa[t * 136 + rr];
            af[ma][1] = xa[t * 136 + rr + 8];
            af[ma][2] = xa[(t + 4) * 136 + rr];
            af[ma][3] = xa[(t + 4) * 136 + rr + 8];
        }
#pragma unroll
        for (int na = 0; na < 8; ++na) {
            int n = wc * 64 + na * 8 + g;
            uint32_t bf[2];
            bf[0] = wb[t * 136 + n];
            bf[1] = wb[(t + 4) * 136 + n];
#pragma unroll
            for (int ma = 0; ma < 2; ++ma) mma_bf16(acc[ma][na], af[ma], bf);
        }
    }
#pragma unroll
    for (int ma = 0; ma < 2; ++ma) {
        int r0 = wr * 32 + ma * 16 + g;
#pragma unroll
        for (int na = 0; na < 8; ++na) {
            int c = wc * 64 + na * 8 + 2 * t;
            int kp = wc * 32 + na * 4 + t;
            float b0 = be[c], b1 = be[c + 1];
            As[kp * 136 + r0] =
                pack_bf16x2(fmaxf(acc[ma][na][0] + b0, 0.f), fmaxf(acc[ma][na][1] + b1, 0.f));
            As[kp * 136 + r0 + 8] =
                pack_bf16x2(fmaxf(acc[ma][na][2] + b0, 0.f), fmaxf(acc[ma][na][3] + b1, 0.f));
        }
    }
#pragma unroll
    for (int i = 0; i < 32; ++i) {
        int idx = tid + i * 256;
        int kp = idx >> 7, n = idx & 127;
        Bs[kp * 136 + n] = pack_bf16x2(Wg0[(size_t)(2 * kp) * 128 + n],
                                       Wg0[(size_t)(2 * kp + 1) * 128 + n]);
    }
    __syncthreads();

#pragma unroll
    for (int ma = 0; ma < 2; ++ma)
#pragma unroll
        for (int na = 0; na < 8; ++na)
#pragma unroll
            for (int q = 0; q < 4; ++q) acc[ma][na][q] = 0.f;

#pragma unroll
    for (int ks = 0; ks < 8; ++ks) {
        int kpb = ks * 8;
        uint32_t af[2][4];
#pragma unroll
        for (int ma = 0; ma < 2; ++ma) {
            int rr = wr * 32 + ma * 16 + g;
            af[ma][0] = As[(kpb + t) * 136 + rr];
            af[ma][1] = As[(kpb + t) * 136 + rr + 8];
            af[ma][2] = As[(kpb + t + 4) * 136 + rr];
            af[ma][3] = As[(kpb + t + 4) * 136 + rr + 8];
        }
#pragma unroll
        for (int na = 0; na < 8; ++na) {
            int n = wc * 64 + na * 8 + g;
            uint32_t bf[2];
            bf[0] = Bs[(kpb + t) * 136 + n];
            bf[1] = Bs[(kpb + t + 4) * 136 + n];
#pragma unroll
            for (int ma = 0; ma < 2; ++ma) mma_bf16(acc[ma][na], af[ma], bf);
        }
    }
#pragma unroll
    for (int ma = 0; ma < 2; ++ma) {
        int r0 = rowBase + wr * 32 + ma * 16 + g;
#pragma unroll
        for (int na = 0; na < 8; ++na) {
            int col = wc * 64 + na * 8 + 2 * t;
            if (r0 < nRows)
                *(uint32_t*)(C + (size_t)r0 * 128 + col) = pack_bf16x2(acc[ma][na][0], acc[ma][na][1]);
            if (r0 + 8 < nRows)
                *(uint32_t*)(C + (size_t)(r0 + 8) * 128 + col) = pack_bf16x2(acc[ma][na][2], acc[ma][na][3]);
        }
    }
}

// ============ bf16 GEMM1 (PDL consumer of agg128) ============
#define G64_AS 0
#define G64_BS (G64_AS + 64 * 136)
#define G64_WORDS (G64_BS + 64 * 72)

__global__ __launch_bounds__(256) void k_gemm64(
    const __nv_bfloat16* __restrict__ A, const float* __restrict__ W,
    __nv_bfloat16* __restrict__ C, int nRows) {
    extern __shared__ uint32_t sm[];
    uint32_t* As = sm + G64_AS;
    uint32_t* Bs = sm + G64_BS;

    int tid = threadIdx.x;
    int lane = tid & 31;
    int wid = tid >> 5;
    int g = lane >> 2, t = lane & 3;
    int wr = wid & 3;
    int wc = wid >> 2;
    int rowBase = blockIdx.x * 128;

    // independent prologue: Wg1 -> Bs
#pragma unroll
    for (int i = 0; i < 16; ++i) {
        int idx = tid + i * 256;
        int kp = idx >> 6;
        int n = idx & 63;
        Bs[kp * 72 + n] = pack_bf16x2(W[(size_t)(2 * kp) * 64 + n],
                                      W[(size_t)(2 * kp + 1) * 64 + n]);
    }
    cudaGridDependencySynchronize();   // wait for agg128 results (h1)

    const uint32_t* Aw = (const uint32_t*)(A + (size_t)rowBase * 128);
    int rowsHere = nRows - rowBase; if (rowsHere > 128) rowsHere = 128;
#pragma unroll
    for (int i = 0; i < 32; ++i) {
        int idx = tid + i * 256;
        int rr = idx >> 6;
        int kp = idx & 63;
        uint32_t v = 0;
        if (rr < rowsHere) v = Aw[idx];
        As[kp * 136 + rr] = v;
    }
    __syncthreads();

    float acc[2][4][4];
#pragma unroll
    for (int ma = 0; ma < 2; ++ma)
#pragma unroll
        for (int na = 0; na < 4; ++na)
#pragma unroll
            for (int q = 0; q < 4; ++q) acc[ma][na][q] = 0.f;

#pragma unroll
    for (int ks = 0; ks < 8; ++ks) {
        int kpb = ks * 8;
        uint32_t af[2][4];
#pragma unroll
        for (int ma = 0; ma < 2; ++ma) {
            int rr = wr * 32 + ma * 16 + g;
            af[ma][0] = As[(kpb + t) * 136 + rr];
            af[ma][1] = As[(kpb + t) * 136 + rr + 8];
            af[ma][2] = As[(kpb + t + 4) * 136 + rr];
            af[ma][3] = As[(kpb + t + 4) * 136 + rr + 8];
        }
#pragma unroll
        for (int na = 0; na < 4; ++na) {
            int n = wc * 32 + na * 8 + g;
            uint32_t bf[2];
            bf[0] = Bs[(kpb + t) * 72 + n];
            bf[1] = Bs[(kpb + t + 4) * 72 + n];
#pragma unroll
            for (int ma = 0; ma < 2; ++ma) mma_bf16(acc[ma][na], af[ma], bf);
        }
    }
#pragma unroll
    for (int ma = 0; ma < 2; ++ma) {
        int r0 = rowBase + wr * 32 + ma * 16 + g;
#pragma unroll
        for (int na = 0; na < 4; ++na) {
            int col = wc * 32 + na * 8 + 2 * t;
            if (r0 < nRows)
                *(uint32_t*)(C + (size_t)r0 * 64 + col) = pack_bf16x2(acc[ma][na][0], acc[ma][na][1]);
            if (r0 + 8 < nRows)
                *(uint32_t*)(C + (size_t)(r0 + 8) * 64 + col) = pack_bf16x2(acc[ma][na][2], acc[ma][na][3]);
        }
    }
}

__device__ __forceinline__ float4 ld_bf16x4(const __nv_bfloat16* base, int lane) {
    uint2 u = ((const uint2*)base)[lane];
    float2 f0 = __bfloat1622float2(*reinterpret_cast<__nv_bfloat162*>(&u.x));
    float2 f1 = __bfloat1622float2(*reinterpret_cast<__nv_bfloat162*>(&u.y));
    return make_float4(f0.x, f0.y, f1.x, f1.y);
}

#define GATHER128(J)                                                        \
    {                                                                       \
        int si = __shfl_sync(0xffffffffu, idx, (J));                        \
        float wv = __shfl_sync(0xffffffffu, dv, (J));                       \
        float4 v = ld_bf16x4(hw + (size_t)si * 128, lane);                  \
        acc.x += v.x * wv; acc.y += v.y * wv;                               \
        acc.z += v.z * wv; acc.w += v.w * wv;                               \
    }

// ================= gather aggregation, D=128 -> h1 (bf16) =================
__global__ void k_agg128(const __nv_bfloat16* __restrict__ hw, const float* __restrict__ b,
                         __nv_bfloat16* __restrict__ outh, int nRows) {
    int n = blockIdx.x * (blockDim.x >> 5) + (threadIdx.x >> 5);
    if (n >= nRows) return;
    int lane = threadIdx.x & 31;
    float di = g_dinv[n];
    float4 acc = ld_bf16x4(hw + (size_t)n * 128, lane);
    float s2 = di * di;
    acc.x *= s2; acc.y *= s2; acc.z *= s2; acc.w *= s2;

    int cnt = g_cnt[n];
    const int* colp = g_col + n * PAD;
    for (int j0 = 0; j0 < cnt; j0 += 32) {
        int c = cnt - j0; if (c > 32) c = 32;
        int idx = 0; float dv = 0.f;
        if (lane < c) { idx = __ldg(colp + j0 + lane); dv = g_dinv[idx] * di; }
        int jj = 0;
        for (; jj + 8 <= c; jj += 8) {
            GATHER128(jj + 0) GATHER128(jj + 1) GATHER128(jj + 2) GATHER128(jj + 3)
            GATHER128(jj + 4) GATHER128(jj + 5) GATHER128(jj + 6) GATHER128(jj + 7)
        }
        for (; jj < c; ++jj) { GATHER128(jj) }
    }
    const float4 bb = ((const float4*)b)[lane];
    uint2 o;
    o.x = pack_bf16x2(fmaxf(acc.x + bb.x, 0.f), fmaxf(acc.y + bb.y, 0.f));
    o.y = pack_bf16x2(fmaxf(acc.z + bb.z, 0.f), fmaxf(acc.w + bb.w, 0.f));
    ((uint2*)(outh + (size_t)n * 128))[lane] = o;
}

#define GATHER64(J)                                                          \
    {                                                                        \
        int si = __shfl_sync(0xffffffffu, idx, (J));                         \
        float wv = __shfl_sync(0xffffffffu, dv, (J));                        \
        uint32_t u = ((const uint32_t*)(hw + (size_t)si * 64))[lane];        \
        float2 v = __bfloat1622float2(*reinterpret_cast<__nv_bfloat162*>(&u)); \
        acc.x += v.x * wv; acc.y += v.y * wv;                                \
    }

// ===== gather aggregation D=64 + fused node head (PDL consumer of gemm64) =====
__global__ void k_agg64_head(const __nv_bfloat16* __restrict__ hw, const float* __restrict__ b,
                             const float* __restrict__ Wsw, const float* __restrict__ Wv,
                             const float* __restrict__ bv, float* __restrict__ out_v,
                             int nRows) {
    int n = blockIdx.x * (blockDim.x >> 5) + (threadIdx.x >> 5);
    int lane = threadIdx.x & 31;
    float di = 0.f;
    int cnt = 0;
    if (n < nRows) { di = g_dinv[n]; cnt = g_cnt[n]; }   // independent prologue
    cudaGridDependencySynchronize();                      // wait for gemm64 (hw1)
    if (n >= nRows) return;

    float2 acc;
    {
        uint32_t u = ((const uint32_t*)(hw + (size_t)n * 64))[lane];
        acc = __bfloat1622float2(*reinterpret_cast<__nv_bfloat162*>(&u));
    }
    float s2 = di * di;
    acc.x *= s2; acc.y *= s2;

    const int* colp = g_col + n * PAD;
    for (int j0 = 0; j0 < cnt; j0 += 32) {
        int c = cnt - j0; if (c > 32) c = 32;
        int idx = 0; float dv = 0.f;
        if (lane < c) { idx = __ldg(colp + j0 + lane); dv = g_dinv[idx] * di; }
        int jj = 0;
        for (; jj + 8 <= c; jj += 8) {
            GATHER64(jj + 0) GATHER64(jj + 1) GATHER64(jj + 2) GATHER64(jj + 3)
            GATHER64(jj + 4) GATHER64(jj + 5) GATHER64(jj + 6) GATHER64(jj + 7)
        }
        for (; jj < c; ++jj) { GATHER64(jj) }
    }
    int c2 = 2 * lane;
    float a0 = fmaxf(acc.x + b[c2], 0.f);
    float a1 = fmaxf(acc.y + b[c2 + 1], 0.f);

    float pp = a0 * Wsw[c2] + a1 * Wsw[c2 + 1];
    float qq = a0 * Wsw[64 + c2] + a1 * Wsw[64 + c2 + 1];
    float vv = a0 * Wv[c2] + a1 * Wv[c2 + 1];
#pragma unroll
    for (int o = 16; o; o >>= 1) {
        pp += __shfl_xor_sync(0xffffffffu, pp, o);
        qq += __shfl_xor_sync(0xffffffffu, qq, o);
        vv += __shfl_xor_sync(0xffffffffu, vv, o);
    }
    if (lane == 0) {
        g_p[n] = pp;
        g_q[n] = qq;
        float vr = 1.f / (1.f + __expf(-(vv + bv[0])));
        float v = 0.9f + 0.2f * vr;
        float vw = fminf(fmaxf(v * v, 0.81f), 1.21f);
        out_v[n] = sqrtf(vw);
    }
}

// ===== per-edge head, 4 edges/thread (PDL consumer of agg64_head) =====
__global__ void k_edge(const int* __restrict__ ei, int E,
                       const float* __restrict__ bsw, float* __restrict__ out) {
    int e = (blockIdx.x * blockDim.x + threadIdx.x) * 4;
    if (e >= E) { cudaGridDependencySynchronize(); return; }
    float bb = __ldg(bsw);
    if (e + 4 <= E) {
        int4 s4 = *(const int4*)(ei + e);
        int4 d4 = *(const int4*)(ei + E + e);
        cudaGridDependencySynchronize();   // wait for p/q
        float4 r;
        {
            float z = __ldg(&g_p[s4.x]) + __ldg(&g_q[d4.x]) + bb;
            r.x = fminf(fmaxf(1.f / (1.f + __expf(-z)), 0.f), 1.f);
        }
        {
            float z = __ldg(&g_p[s4.y]) + __ldg(&g_q[d4.y]) + bb;
            r.y = fminf(fmaxf(1.f / (1.f + __expf(-z)), 0.f), 1.f);
        }
        {
            float z = __ldg(&g_p[s4.z]) + __ldg(&g_q[d4.z]) + bb;
            r.z = fminf(fmaxf(1.f / (1.f + __expf(-z)), 0.f), 1.f);
        }
        {
            float z = __ldg(&g_p[s4.w]) + __ldg(&g_q[d4.w]) + bb;
            r.w = fminf(fmaxf(1.f / (1.f + __expf(-z)), 0.f), 1.f);
        }
        *(float4*)(out + e) = r;
    } else {
        cudaGridDependencySynchronize();
        for (; e < E; ++e) {
            float z = __ldg(&g_p[ei[e]]) + __ldg(&g_q[ei[E + e]]) + bb;
            out[e] = fminf(fmaxf(1.f / (1.f + __expf(-z)), 0.f), 1.f);
        }
    }
}

extern "C" void kernel_launch(void* const* d_in, const int* in_sizes, int n_in,
                              void* d_out, int out_size) {
    const float* x     = (const float*)d_in[0];
    const int*   ei    = (const int*)d_in[1];
    const float* W_enc = (const float*)d_in[2];
    const float* b_enc = (const float*)d_in[3];
    const float* W_g0  = (const float*)d_in[4];
    const float* b_g0  = (const float*)d_in[5];
    const float* W_g1  = (const float*)d_in[6];
    const float* b_g1  = (const float*)d_in[7];
    const float* W_sw  = (const float*)d_in[8];
    const float* b_sw  = (const float*)d_in[9];
    const float* W_v   = (const float*)d_in[10];
    const float* b_v   = (const float*)d_in[11];
    float* out = (float*)d_out;

    const int N = in_sizes[0] / 16;
    const int E = in_sizes[1] / 2;

    __nv_bfloat16 *p_hw0, *p_h1, *p_hw1;
    cudaGetSymbolAddress((void**)&p_hw0, g_hw0);
    cudaGetSymbolAddress((void**)&p_h1, g_h1);
    cudaGetSymbolAddress((void**)&p_hw1, g_hw1);

    static cudaStream_t s_side = nullptr;
    static cudaEvent_t s_fork = nullptr, s_join = nullptr;
    if (s_side == nullptr) {
        cudaStreamCreateWithFlags(&s_side, cudaStreamNonBlocking);
        cudaEventCreateWithFlags(&s_fork, cudaEventDisableTiming);
        cudaEventCreateWithFlags(&s_join, cudaEventDisableTiming);
        cudaFuncSetAttribute(k_enc_gemm0, cudaFuncAttributeMaxDynamicSharedMemorySize,
                             EG0_WORDS * 4);
        cudaFuncSetAttribute(k_gemm64, cudaFuncAttributeMaxDynamicSharedMemorySize,
                             G64_WORDS * 4);
    }

    // ---- fork: adjacency build on side stream, encoder+GEMM0 on main ----
    cudaEventRecord(s_fork, 0);
    cudaStreamWaitEvent(s_side, s_fork, 0);

    k_zero<<<(N + 255) / 256, 256, 0, s_side>>>(N);
    k_fill<<<(E + 255) / 256, 256, 0, s_side>>>(ei, E);
    k_dinv<<<(N + 255) / 256, 256, 0, s_side>>>(N);
    cudaEventRecord(s_join, s_side);

    k_enc_gemm0<<<(N + 127) / 128, 256, EG0_WORDS * 4>>>(x, W_enc, b_enc, W_g0, p_hw0, N);

    // ---- join ----
    cudaStreamWaitEvent(0, s_join, 0);

    // ---- layer 0 aggregation ----
    k_agg128<<<(N + 7) / 8, 256>>>(p_hw0, b_g0, p_h1, N);

    // ---- PDL launch config helper ----
    cudaLaunchAttribute pdlAttr[1];
    pdlAttr[0].id = cudaLaunchAttributeProgrammaticStreamSerialization;
    pdlAttr[0].val.programmaticStreamSerializationAllowed = 1;

    // ---- layer 1 GEMM (PDL after agg128) ----
    {
        cudaLaunchConfig_t cfg = {};
        cfg.gridDim = dim3((N + 127) / 128);
        cfg.blockDim = dim3(256);
        cfg.dynamicSmemBytes = G64_WORDS * 4;
        cfg.stream = 0;
        cfg.attrs = pdlAttr;
        cfg.numAttrs = 1;
        cudaLaunchKernelEx(&cfg, k_gemm64, (const __nv_bfloat16*)p_h1, W_g1,
                           (__nv_bfloat16*)p_hw1, N);
    }

    // ---- layer 1 agg + node head (PDL after gemm64) ----
    {
        cudaLaunchConfig_t cfg = {};
        cfg.gridDim = dim3((N + 7) / 8);
        cfg.blockDim = dim3(256);
        cfg.stream = 0;
        cfg.attrs = pdlAttr;
        cfg.numAttrs = 1;
        cudaLaunchKernelEx(&cfg, k_agg64_head, (const __nv_bfloat16*)p_hw1, b_g1,
                           W_sw, W_v, b_v, out + E, N);
    }

    // ---- per-edge head (PDL after agg64_head) ----
    {
        int nThreads = (E + 3) / 4;
        cudaLaunchConfig_t cfg = {};
        cfg.gridDim = dim3((nThreads + 255) / 256);
        cfg.blockDim = dim3(256);
        cfg.stream = 0;
        cfg.attrs = pdlAttr;
        cfg.numAttrs = 1;
        cudaLaunchKernelEx(&cfg, k_edge, ei, E, b_sw, out);
    }
}

// round 14
// speedup vs baseline: 1.1438x; 1.0730x over previous
#include <cuda_runtime.h>
#include <cuda_bf16.h>
#include <cuda_fp16.h>
#include <cstdint>
#include <math.h>

#define MAXN 100000
#define PAD 64

// ---- static scratch ----
__device__ uint8_t       g_hw0[MAXN * 128];  // messages layer 0 (e4m3 fp8)
__device__ __nv_bfloat16 g_h1 [MAXN * 128];  // relu(agg0 + b0), bf16
__device__ __nv_bfloat16 g_hw1[MAXN * 64];   // messages layer 1 (bf16)
__device__ float g_dinv[MAXN];
__device__ int   g_cnt [MAXN];
__device__ int   g_col [MAXN * PAD];
__device__ float g_p[MAXN];
__device__ float g_q[MAXN];

__device__ __forceinline__ uint32_t pack_bf16x2(float lo, float hi) {
    __nv_bfloat162 h = __floats2bfloat162_rn(lo, hi);
    return *reinterpret_cast<uint32_t*>(&h);
}

__device__ __forceinline__ unsigned short pack_e4m3x2(float lo, float hi) {
    unsigned short u;
    asm("cvt.rn.satfinite.e4m3x2.f32 %0, %1, %2;" : "=h"(u) : "f"(hi), "f"(lo));
    return u;
}

__device__ __forceinline__ float4 fp8x4_to_float4(uint32_t u) {
    uint32_t f01, f23;
    asm("cvt.rn.f16x2.e4m3x2 %0, %1;" : "=r"(f01) : "h"((unsigned short)(u & 0xffffu)));
    asm("cvt.rn.f16x2.e4m3x2 %0, %1;" : "=r"(f23) : "h"((unsigned short)(u >> 16)));
    float2 v01 = __half22float2(*reinterpret_cast<__half2*>(&f01));
    float2 v23 = __half22float2(*reinterpret_cast<__half2*>(&f23));
    return make_float4(v01.x, v01.y, v23.x, v23.y);
}

__device__ __forceinline__ void mma_bf16(float c[4], const uint32_t a[4], const uint32_t b[2]) {
    asm volatile(
        "mma.sync.aligned.m16n8k16.row.col.f32.bf16.bf16.f32 "
        "{%0,%1,%2,%3}, {%4,%5,%6,%7}, {%8,%9}, {%0,%1,%2,%3};"
        : "+f"(c[0]), "+f"(c[1]), "+f"(c[2]), "+f"(c[3])
        : "r"(a[0]), "r"(a[1]), "r"(a[2]), "r"(a[3]), "r"(b[0]), "r"(b[1]));
}

// ================= padded adjacency build =================
__global__ void k_zero(int n) {
    int i = blockIdx.x * blockDim.x + threadIdx.x;
    if (i < n) g_cnt[i] = 0;
}

__global__ void k_fill(const int* __restrict__ ei, int E) {
    int e = blockIdx.x * blockDim.x + threadIdx.x;
    if (e >= E) return;
    int s = ei[e];
    int d = ei[E + e];
    int pos = atomicAdd(&g_cnt[d], 1);
    g_col[d * PAD + pos] = s;
}

__global__ void k_dinv(int n) {
    int i = blockIdx.x * blockDim.x + threadIdx.x;
    if (i < n) g_dinv[i] = rsqrtf((float)(g_cnt[i] + 1));
}

// ===== fully-tensor fused encoder + GEMM0: hw0 = fp8(relu(x Wenc + b) @ Wg0) =====
#define EG0_XA 0
#define EG0_WB (EG0_XA + 8 * 136)
#define EG0_BE (EG0_WB + 8 * 136)
#define EG0_AS (EG0_BE + 128)
#define EG0_BS (EG0_AS + 64 * 136)
#define EG0_WORDS (EG0_BS + 64 * 136)

__global__ __launch_bounds__(256) void k_enc_gemm0(
    const float* __restrict__ x, const float* __restrict__ Wenc,
    const float* __restrict__ benc, const float* __restrict__ Wg0,
    uint8_t* __restrict__ C, int nRows) {
    extern __shared__ uint32_t sm[];
    uint32_t* xa = sm + EG0_XA;
    uint32_t* wb = sm + EG0_WB;
    float*    be = (float*)(sm + EG0_BE);
    uint32_t* As = sm + EG0_AS;
    uint32_t* Bs = sm + EG0_BS;

    int tid = threadIdx.x;
    int lane = tid & 31;
    int wid = tid >> 5;
    int g = lane >> 2, t = lane & 3;
    int wr = wid & 3;
    int wc = wid >> 2;
    int rowBase = blockIdx.x * 128;

    {
        int r = tid >> 1, q = tid & 1;
        int gr = rowBase + r;
        float4 v0 = make_float4(0.f, 0.f, 0.f, 0.f), v1 = v0;
        if (gr < nRows) {
            v0 = *(const float4*)(x + (size_t)gr * 16 + q * 8);
            v1 = *(const float4*)(x + (size_t)gr * 16 + q * 8 + 4);
        }
        xa[(q * 4 + 0) * 136 + r] = pack_bf16x2(v0.x, v0.y);
        xa[(q * 4 + 1) * 136 + r] = pack_bf16x2(v0.z, v0.w);
        xa[(q * 4 + 2) * 136 + r] = pack_bf16x2(v1.x, v1.y);
        xa[(q * 4 + 3) * 136 + r] = pack_bf16x2(v1.z, v1.w);
    }
#pragma unroll
    for (int i = 0; i < 4; ++i) {
        int idx = tid + i * 256;
        int kp = idx >> 7, n = idx & 127;
        wb[kp * 136 + n] = pack_bf16x2(Wenc[(size_t)(2 * kp) * 128 + n],
                                       Wenc[(size_t)(2 * kp + 1) * 128 + n]);
    }
    if (tid < 128) be[tid] = benc[tid];
    __syncthreads();

    float acc[2][8][4];
#pragma unroll
    for (int ma = 0; ma < 2; ++ma)
#pragma unroll
        for (int na = 0; na < 8; ++na)
#pragma unroll
            for (int q = 0; q < 4; ++q) acc[ma][na][q] = 0.f;
    {
        uint32_t af[2][4];
#pragma unroll
        for (int ma = 0; ma < 2; ++ma) {
            int rr = wr * 32 + ma * 16 + g;
            af[ma][0] = xa[t * 136 + rr];
            af[ma][1] = xa[t * 136 + rr + 8];
            af[ma][2] = xa[(t + 4) * 136 + rr];
            af[ma][3] = xa[(t + 4) * 136 + rr + 8];
        }
#pragma unroll
        for (int na = 0; na < 8; ++na) {
            int n = wc * 64 + na * 8 + g;
            uint32_t bf[2];
            bf[0] = wb[t * 136 + n];
            bf[1] = wb[(t + 4) * 136 + n];
#pragma unroll
            for (int ma = 0; ma < 2; ++ma) mma_bf16(acc[ma][na], af[ma], bf);
        }
    }
#pragma unroll
    for (int ma = 0; ma < 2; ++ma) {
        int r0 = wr * 32 + ma * 16 + g;
#pragma unroll
        for (int na = 0; na < 8; ++na) {
            int c = wc * 64 + na * 8 + 2 * t;
            int kp = wc * 32 + na * 4 + t;
            float b0 = be[c], b1 = be[c + 1];
            As[kp * 136 + r0] =
                pack_bf16x2(fmaxf(acc[ma][na][0] + b0, 0.f), fmaxf(acc[ma][na][1] + b1, 0.f));
            As[kp * 136 + r0 + 8] =
                pack_bf16x2(fmaxf(acc[ma][na][2] + b0, 0.f), fmaxf(acc[ma][na][3] + b1, 0.f));
        }
    }
#pragma unroll
    for (int i = 0; i < 32; ++i) {
        int idx = tid + i * 256;
        int kp = idx >> 7, n = idx & 127;
        Bs[kp * 136 + n] = pack_bf16x2(Wg0[(size_t)(2 * kp) * 128 + n],
                                       Wg0[(size_t)(2 * kp + 1) * 128 + n]);
    }
    __syncthreads();

#pragma unroll
    for (int ma = 0; ma < 2; ++ma)
#pragma unroll
        for (int na = 0; na < 8; ++na)
#pragma unroll
            for (int q = 0; q < 4; ++q) acc[ma][na][q] = 0.f;

#pragma unroll
    for (int ks = 0; ks < 8; ++ks) {
        int kpb = ks * 8;
        uint32_t af[2][4];
#pragma unroll
        for (int ma = 0; ma < 2; ++ma) {
            int rr = wr * 32 + ma * 16 + g;
            af[ma][0] = As[(kpb + t) * 136 + rr];
            af[ma][1] = As[(kpb + t) * 136 + rr + 8];
            af[ma][2] = As[(kpb + t + 4) * 136 + rr];
            af[ma][3] = As[(kpb + t + 4) * 136 + rr + 8];
        }
#pragma unroll
        for (int na = 0; na < 8; ++na) {
            int n = wc * 64 + na * 8 + g;
            uint32_t bf[2];
            bf[0] = Bs[(kpb + t) * 136 + n];
            bf[1] = Bs[(kpb + t + 4) * 136 + n];
#pragma unroll
            for (int ma = 0; ma < 2; ++ma) mma_bf16(acc[ma][na], af[ma], bf);
        }
    }
    // epilogue: pack fp8, merge t-lane pairs so even-t lanes do 4B stores
#pragma unroll
    for (int ma = 0; ma < 2; ++ma) {
        int r0 = rowBase + wr * 32 + ma * 16 + g;
#pragma unroll
        for (int na = 0; na < 8; ++na) {
            unsigned short u0 = pack_e4m3x2(acc[ma][na][0], acc[ma][na][1]);
            unsigned short u1 = pack_e4m3x2(acc[ma][na][2], acc[ma][na][3]);
            uint32_t o0 = __shfl_xor_sync(0xffffffffu, (uint32_t)u0, 1);
            uint32_t o1 = __shfl_xor_sync(0xffffffffu, (uint32_t)u1, 1);
            if ((t & 1) == 0) {
                uint32_t w0 = (uint32_t)u0 | (o0 << 16);
                uint32_t w1 = (uint32_t)u1 | (o1 << 16);
                int colB = wc * 64 + na * 8 + 2 * t;   // 4-aligned for even t
                if (r0 < nRows)
                    *(uint32_t*)(C + (size_t)r0 * 128 + colB) = w0;
                if (r0 + 8 < nRows)
                    *(uint32_t*)(C + (size_t)(r0 + 8) * 128 + colB) = w1;
            }
        }
    }
}

// ============ bf16 GEMM1 (A already bf16): hw1 = bf16(h1 @ W_g1) ============
#define G64_AS 0
#define G64_BS (G64_AS + 64 * 136)
#define G64_WORDS (G64_BS + 64 * 72)

__global__ __launch_bounds__(256) void k_gemm64(
    const __nv_bfloat16* __restrict__ A, const float* __restrict__ W,
    __nv_bfloat16* __restrict__ C, int nRows) {
    extern __shared__ uint32_t sm[];
    uint32_t* As = sm + G64_AS;
    uint32_t* Bs = sm + G64_BS;

    int tid = threadIdx.x;
    int lane = tid & 31;
    int wid = tid >> 5;
    int g = lane >> 2, t = lane & 3;
    int wr = wid & 3;
    int wc = wid >> 2;
    int rowBase = blockIdx.x * 128;

    const uint32_t* Aw = (const uint32_t*)(A + (size_t)rowBase * 128);
    int rowsHere = nRows - rowBase; if (rowsHere > 128) rowsHere = 128;
#pragma unroll
    for (int i = 0; i < 32; ++i) {
        int idx = tid + i * 256;
        int rr = idx >> 6;
        int kp = idx & 63;
        uint32_t v = 0;
        if (rr < rowsHere) v = Aw[idx];
        As[kp * 136 + rr] = v;
    }
#pragma unroll
    for (int i = 0; i < 16; ++i) {
        int idx = tid + i * 256;
        int kp = idx >> 6;
        int n = idx & 63;
        Bs[kp * 72 + n] = pack_bf16x2(W[(size_t)(2 * kp) * 64 + n],
                                      W[(size_t)(2 * kp + 1) * 64 + n]);
    }
    __syncthreads();

    float acc[2][4][4];
#pragma unroll
    for (int ma = 0; ma < 2; ++ma)
#pragma unroll
        for (int na = 0; na < 4; ++na)
#pragma unroll
            for (int q = 0; q < 4; ++q) acc[ma][na][q] = 0.f;

#pragma unroll
    for (int ks = 0; ks < 8; ++ks) {
        int kpb = ks * 8;
        uint32_t af[2][4];
#pragma unroll
        for (int ma = 0; ma < 2; ++ma) {
            int rr = wr * 32 + ma * 16 + g;
            af[ma][0] = As[(kpb + t) * 136 + rr];
            af[ma][1] = As[(kpb + t) * 136 + rr + 8];
            af[ma][2] = As[(kpb + t + 4) * 136 + rr];
            af[ma][3] = As[(kpb + t + 4) * 136 + rr + 8];
        }
#pragma unroll
        for (int na = 0; na < 4; ++na) {
            int n = wc * 32 + na * 8 + g;
            uint32_t bf[2];
            bf[0] = Bs[(kpb + t) * 72 + n];
            bf[1] = Bs[(kpb + t + 4) * 72 + n];
#pragma unroll
            for (int ma = 0; ma < 2; ++ma) mma_bf16(acc[ma][na], af[ma], bf);
        }
    }
#pragma unroll
    for (int ma = 0; ma < 2; ++ma) {
        int r0 = rowBase + wr * 32 + ma * 16 + g;
#pragma unroll
        for (int na = 0; na < 4; ++na) {
            int col = wc * 32 + na * 8 + 2 * t;
            if (r0 < nRows)
                *(uint32_t*)(C + (size_t)r0 * 64 + col) = pack_bf16x2(acc[ma][na][0], acc[ma][na][1]);
            if (r0 + 8 < nRows)
                *(uint32_t*)(C + (size_t)(r0 + 8) * 64 + col) = pack_bf16x2(acc[ma][na][2], acc[ma][na][3]);
        }
    }
}

#define GATHER128(J)                                                          \
    {                                                                         \
        int si = __shfl_sync(0xffffffffu, idx, (J));                          \
        float wv = __shfl_sync(0xffffffffu, dv, (J));                         \
        uint32_t u = __ldg((const uint32_t*)(hw + (size_t)si * 128) + lane);  \
        float4 v = fp8x4_to_float4(u);                                        \
        acc.x += v.x * wv; acc.y += v.y * wv;                                 \
        acc.z += v.z * wv; acc.w += v.w * wv;                                 \
    }

// ================= gather aggregation, D=128 fp8 messages -> h1 (bf16) =================
__global__ void k_agg128(const uint8_t* __restrict__ hw, const float* __restrict__ b,
                         __nv_bfloat16* __restrict__ outh, int nRows) {
    int n = blockIdx.x * (blockDim.x >> 5) + (threadIdx.x >> 5);
    if (n >= nRows) return;
    int lane = threadIdx.x & 31;
    float di = g_dinv[n];
    float4 acc;
    {
        uint32_t u = __ldg((const uint32_t*)(hw + (size_t)n * 128) + lane);
        acc = fp8x4_to_float4(u);
    }
    float s2 = di * di;
    acc.x *= s2; acc.y *= s2; acc.z *= s2; acc.w *= s2;

    int cnt = g_cnt[n];
    const int* colp = g_col + n * PAD;
    for (int j0 = 0; j0 < cnt; j0 += 32) {
        int c = cnt - j0; if (c > 32) c = 32;
        int idx = 0; float dv = 0.f;
        if (lane < c) { idx = __ldg(colp + j0 + lane); dv = g_dinv[idx] * di; }
        int jj = 0;
        for (; jj + 8 <= c; jj += 8) {
            GATHER128(jj + 0) GATHER128(jj + 1) GATHER128(jj + 2) GATHER128(jj + 3)
            GATHER128(jj + 4) GATHER128(jj + 5) GATHER128(jj + 6) GATHER128(jj + 7)
        }
        for (; jj < c; ++jj) { GATHER128(jj) }
    }
    const float4 bb = ((const float4*)b)[lane];
    uint2 o;
    o.x = pack_bf16x2(fmaxf(acc.x + bb.x, 0.f), fmaxf(acc.y + bb.y, 0.f));
    o.y = pack_bf16x2(fmaxf(acc.z + bb.z, 0.f), fmaxf(acc.w + bb.w, 0.f));
    ((uint2*)(outh + (size_t)n * 128))[lane] = o;
}

#define GATHER64(J)                                                          \
    {                                                                        \
        int si = __shfl_sync(0xffffffffu, idx, (J));                         \
        float wv = __shfl_sync(0xffffffffu, dv, (J));                        \
        uint32_t u = ((const uint32_t*)(hw + (size_t)si * 64))[lane];        \
        float2 v = __bfloat1622float2(*reinterpret_cast<__nv_bfloat162*>(&u)); \
        acc.x += v.x * wv; acc.y += v.y * wv;                                \
    }

// ===== gather aggregation D=64 + fused node head =====
__global__ void k_agg64_head(const __nv_bfloat16* __restrict__ hw, const float* __restrict__ b,
                             const float* __restrict__ Wsw, const float* __restrict__ Wv,
                             const float* __restrict__ bv, float* __restrict__ out_v,
                             int nRows) {
    int n = blockIdx.x * (blockDim.x >> 5) + (threadIdx.x >> 5);
    if (n >= nRows) return;
    int lane = threadIdx.x & 31;
    float di = g_dinv[n];
    float2 acc;
    {
        uint32_t u = ((const uint32_t*)(hw + (size_t)n * 64))[lane];
        acc = __bfloat1622float2(*reinterpret_cast<__nv_bfloat162*>(&u));
    }
    float s2 = di * di;
    acc.x *= s2; acc.y *= s2;

    int cnt = g_cnt[n];
    const int* colp = g_col + n * PAD;
    for (int j0 = 0; j0 < cnt; j0 += 32) {
        int c = cnt - j0; if (c > 32) c = 32;
        int idx = 0; float dv = 0.f;
        if (lane < c) { idx = __ldg(colp + j0 + lane); dv = g_dinv[idx] * di; }
        int jj = 0;
        for (; jj + 8 <= c; jj += 8) {
            GATHER64(jj + 0) GATHER64(jj + 1) GATHER64(jj + 2) GATHER64(jj + 3)
            GATHER64(jj + 4) GATHER64(jj + 5) GATHER64(jj + 6) GATHER64(jj + 7)
        }
        for (; jj < c; ++jj) { GATHER64(jj) }
    }
    int c2 = 2 * lane;
    float a0 = fmaxf(acc.x + b[c2], 0.f);
    float a1 = fmaxf(acc.y + b[c2 + 1], 0.f);

    float pp = a0 * Wsw[c2] + a1 * Wsw[c2 + 1];
    float qq = a0 * Wsw[64 + c2] + a1 * Wsw[64 + c2 + 1];
    float vv = a0 * Wv[c2] + a1 * Wv[c2 + 1];
#pragma unroll
    for (int o = 16; o; o >>= 1) {
        pp += __shfl_xor_sync(0xffffffffu, pp, o);
        qq += __shfl_xor_sync(0xffffffffu, qq, o);
        vv += __shfl_xor_sync(0xffffffffu, vv, o);
    }
    if (lane == 0) {
        g_p[n] = pp;
        g_q[n] = qq;
        float vr = 1.f / (1.f + __expf(-(vv + bv[0])));
        float v = 0.9f + 0.2f * vr;
        float vw = fminf(fmaxf(v * v, 0.81f), 1.21f);
        out_v[n] = sqrtf(vw);
    }
}

// ===== per-edge head, 4 edges/thread =====
__global__ void k_edge(const int* __restrict__ ei, int E,
                       const float* __restrict__ bsw, float* __restrict__ out) {
    int e = (blockIdx.x * blockDim.x + threadIdx.x) * 4;
    if (e >= E) return;
    float bb = __ldg(bsw);
    if (e + 4 <= E) {
        int4 s4 = *(const int4*)(ei + e);
        int4 d4 = *(const int4*)(ei + E + e);
        float4 r;
        {
            float z = __ldg(&g_p[s4.x]) + __ldg(&g_q[d4.x]) + bb;
            r.x = fminf(fmaxf(1.f / (1.f + __expf(-z)), 0.f), 1.f);
        }
        {
            float z = __ldg(&g_p[s4.y]) + __ldg(&g_q[d4.y]) + bb;
            r.y = fminf(fmaxf(1.f / (1.f + __expf(-z)), 0.f), 1.f);
        }
        {
            float z = __ldg(&g_p[s4.z]) + __ldg(&g_q[d4.z]) + bb;
            r.z = fminf(fmaxf(1.f / (1.f + __expf(-z)), 0.f), 1.f);
        }
        {
            float z = __ldg(&g_p[s4.w]) + __ldg(&g_q[d4.w]) + bb;
            r.w = fminf(fmaxf(1.f / (1.f + __expf(-z)), 0.f), 1.f);
        }
        *(float4*)(out + e) = r;
    } else {
        for (; e < E; ++e) {
            float z = __ldg(&g_p[ei[e]]) + __ldg(&g_q[ei[E + e]]) + bb;
            out[e] = fminf(fmaxf(1.f / (1.f + __expf(-z)), 0.f), 1.f);
        }
    }
}

extern "C" void kernel_launch(void* const* d_in, const int* in_sizes, int n_in,
                              void* d_out, int out_size) {
    const float* x     = (const float*)d_in[0];
    const int*   ei    = (const int*)d_in[1];
    const float* W_enc = (const float*)d_in[2];
    const float* b_enc = (const float*)d_in[3];
    const float* W_g0  = (const float*)d_in[4];
    const float* b_g0  = (const float*)d_in[5];
    const float* W_g1  = (const float*)d_in[6];
    const float* b_g1  = (const float*)d_in[7];
    const float* W_sw  = (const float*)d_in[8];
    const float* b_sw  = (const float*)d_in[9];
    const float* W_v   = (const float*)d_in[10];
    const float* b_v   = (const float*)d_in[11];
    float* out = (float*)d_out;

    const int N = in_sizes[0] / 16;
    const int E = in_sizes[1] / 2;

    uint8_t* p_hw0;
    __nv_bfloat16 *p_h1, *p_hw1;
    cudaGetSymbolAddress((void**)&p_hw0, g_hw0);
    cudaGetSymbolAddress((void**)&p_h1, g_h1);
    cudaGetSymbolAddress((void**)&p_hw1, g_hw1);

    static cudaStream_t s_side = nullptr;
    static cudaEvent_t s_fork = nullptr, s_join = nullptr;
    if (s_side == nullptr) {
        cudaStreamCreateWithFlags(&s_side, cudaStreamNonBlocking);
        cudaEventCreateWithFlags(&s_fork, cudaEventDisableTiming);
        cudaEventCreateWithFlags(&s_join, cudaEventDisableTiming);
        cudaFuncSetAttribute(k_enc_gemm0, cudaFuncAttributeMaxDynamicSharedMemorySize,
                             EG0_WORDS * 4);
        cudaFuncSetAttribute(k_gemm64, cudaFuncAttributeMaxDynamicSharedMemorySize,
                             G64_WORDS * 4);
    }

    // ---- fork: adjacency build on side stream, encoder+GEMM0 on main ----
    cudaEventRecord(s_fork, 0);
    cudaStreamWaitEvent(s_side, s_fork, 0);

    k_zero<<<(N + 255) / 256, 256, 0, s_side>>>(N);
    k_fill<<<(E + 255) / 256, 256, 0, s_side>>>(ei, E);
    k_dinv<<<(N + 255) / 256, 256, 0, s_side>>>(N);
    cudaEventRecord(s_join, s_side);

    k_enc_gemm0<<<(N + 127) / 128, 256, EG0_WORDS * 4>>>(x, W_enc, b_enc, W_g0, p_hw0, N);

    // ---- join ----
    cudaStreamWaitEvent(0, s_join, 0);

    // ---- layer 0 aggregation (fp8 messages) ----
    k_agg128<<<(N + 7) / 8, 256>>>(p_hw0, b_g0, p_h1, N);

    // ---- layer 1 ----
    k_gemm64<<<(N + 127) / 128, 256, G64_WORDS * 4>>>(p_h1, W_g1, p_hw1, N);
    k_agg64_head<<<(N + 7) / 8, 256>>>(p_hw1, b_g1, W_sw, W_v, b_v, out + E, N);

    // ---- per-edge head ----
    k_edge<<<((E + 3) / 4 + 255) / 256, 256>>>(ei, E, b_sw, out);
}

// round 15
// speedup vs baseline: 1.1822x; 1.0335x over previous
#include <cuda_runtime.h>
#include <cuda_bf16.h>
#include <cuda_fp16.h>
#include <cstdint>
#include <math.h>

#define MAXN 100000
#define PAD 64

// ---- static scratch ----
__device__ uint8_t       g_hw0[MAXN * 128];  // messages layer 0 (e4m3)
__device__ __nv_bfloat16 g_h1 [MAXN * 128];  // relu(agg0 + b0), bf16
__device__ uint8_t       g_hw1[MAXN * 64];   // messages layer 1 (e4m3)
__device__ float g_dinv[MAXN];
__device__ int   g_cnt [MAXN];
__device__ int   g_col [MAXN * PAD];
__device__ float g_p[MAXN];
__device__ float g_q[MAXN];

__device__ __forceinline__ uint32_t pack_bf16x2(float lo, float hi) {
    __nv_bfloat162 h = __floats2bfloat162_rn(lo, hi);
    return *reinterpret_cast<uint32_t*>(&h);
}

__device__ __forceinline__ unsigned short pack_e4m3x2(float lo, float hi) {
    unsigned short u;
    asm("cvt.rn.satfinite.e4m3x2.f32 %0, %1, %2;" : "=h"(u) : "f"(hi), "f"(lo));
    return u;
}

__device__ __forceinline__ float2 fp8x2_to_float2(unsigned short u) {
    uint32_t f01;
    asm("cvt.rn.f16x2.e4m3x2 %0, %1;" : "=r"(f01) : "h"(u));
    return __half22float2(*reinterpret_cast<__half2*>(&f01));
}

__device__ __forceinline__ float4 fp8x4_to_float4(uint32_t u) {
    float2 v01 = fp8x2_to_float2((unsigned short)(u & 0xffffu));
    float2 v23 = fp8x2_to_float2((unsigned short)(u >> 16));
    return make_float4(v01.x, v01.y, v23.x, v23.y);
}

__device__ __forceinline__ void mma_bf16(float c[4], const uint32_t a[4], const uint32_t b[2]) {
    asm volatile(
        "mma.sync.aligned.m16n8k16.row.col.f32.bf16.bf16.f32 "
        "{%0,%1,%2,%3}, {%4,%5,%6,%7}, {%8,%9}, {%0,%1,%2,%3};"
        : "+f"(c[0]), "+f"(c[1]), "+f"(c[2]), "+f"(c[3])
        : "r"(a[0]), "r"(a[1]), "r"(a[2]), "r"(a[3]), "r"(b[0]), "r"(b[1]));
}

// ================= padded adjacency build =================
__global__ void k_zero(int n) {
    int i = blockIdx.x * blockDim.x + threadIdx.x;
    if (i < n) g_cnt[i] = 0;
}

__global__ void k_fill(const int* __restrict__ ei, int E) {
    int e = blockIdx.x * blockDim.x + threadIdx.x;
    if (e >= E) return;
    int s = ei[e];
    int d = ei[E + e];
    int pos = atomicAdd(&g_cnt[d], 1);
    g_col[d * PAD + pos] = s;
}

__global__ void k_dinv(int n) {
    int i = blockIdx.x * blockDim.x + threadIdx.x;
    if (i < n) g_dinv[i] = rsqrtf((float)(g_cnt[i] + 1));
}

// ===== fully-tensor fused encoder + GEMM0: hw0 = fp8(relu(x Wenc + b) @ Wg0) =====
#define EG0_XA 0
#define EG0_WB (EG0_XA + 8 * 136)
#define EG0_BE (EG0_WB + 8 * 136)
#define EG0_AS (EG0_BE + 128)
#define EG0_BS (EG0_AS + 64 * 136)
#define EG0_WORDS (EG0_BS + 64 * 136)

__global__ __launch_bounds__(256) void k_enc_gemm0(
    const float* __restrict__ x, const float* __restrict__ Wenc,
    const float* __restrict__ benc, const float* __restrict__ Wg0,
    uint8_t* __restrict__ C, int nRows) {
    extern __shared__ uint32_t sm[];
    uint32_t* xa = sm + EG0_XA;
    uint32_t* wb = sm + EG0_WB;
    float*    be = (float*)(sm + EG0_BE);
    uint32_t* As = sm + EG0_AS;
    uint32_t* Bs = sm + EG0_BS;

    int tid = threadIdx.x;
    int lane = tid & 31;
    int wid = tid >> 5;
    int g = lane >> 2, t = lane & 3;
    int wr = wid & 3;
    int wc = wid >> 2;
    int rowBase = blockIdx.x * 128;

    {
        int r = tid >> 1, q = tid & 1;
        int gr = rowBase + r;
        float4 v0 = make_float4(0.f, 0.f, 0.f, 0.f), v1 = v0;
        if (gr < nRows) {
            v0 = *(const float4*)(x + (size_t)gr * 16 + q * 8);
            v1 = *(const float4*)(x + (size_t)gr * 16 + q * 8 + 4);
        }
        xa[(q * 4 + 0) * 136 + r] = pack_bf16x2(v0.x, v0.y);
        xa[(q * 4 + 1) * 136 + r] = pack_bf16x2(v0.z, v0.w);
        xa[(q * 4 + 2) * 136 + r] = pack_bf16x2(v1.x, v1.y);
        xa[(q * 4 + 3) * 136 + r] = pack_bf16x2(v1.z, v1.w);
    }
#pragma unroll
    for (int i = 0; i < 4; ++i) {
        int idx = tid + i * 256;
        int kp = idx >> 7, n = idx & 127;
        wb[kp * 136 + n] = pack_bf16x2(Wenc[(size_t)(2 * kp) * 128 + n],
                                       Wenc[(size_t)(2 * kp + 1) * 128 + n]);
    }
    if (tid < 128) be[tid] = benc[tid];
    __syncthreads();

    float acc[2][8][4];
#pragma unroll
    for (int ma = 0; ma < 2; ++ma)
#pragma unroll
        for (int na = 0; na < 8; ++na)
#pragma unroll
            for (int q = 0; q < 4; ++q) acc[ma][na][q] = 0.f;
    {
        uint32_t af[2][4];
#pragma unroll
        for (int ma = 0; ma < 2; ++ma) {
            int rr = wr * 32 + ma * 16 + g;
            af[ma][0] = xa[t * 136 + rr];
            af[ma][1] = xa[t * 136 + rr + 8];
            af[ma][2] = xa[(t + 4) * 136 + rr];
            af[ma][3] = xa[(t + 4) * 136 + rr + 8];
        }
#pragma unroll
        for (int na = 0; na < 8; ++na) {
            int n = wc * 64 + na * 8 + g;
            uint32_t bf[2];
            bf[0] = wb[t * 136 + n];
            bf[1] = wb[(t + 4) * 136 + n];
#pragma unroll
            for (int ma = 0; ma < 2; ++ma) mma_bf16(acc[ma][na], af[ma], bf);
        }
    }
#pragma unroll
    for (int ma = 0; ma < 2; ++ma) {
        int r0 = wr * 32 + ma * 16 + g;
#pragma unroll
        for (int na = 0; na < 8; ++na) {
            int c = wc * 64 + na * 8 + 2 * t;
            int kp = wc * 32 + na * 4 + t;
            float b0 = be[c], b1 = be[c + 1];
            As[kp * 136 + r0] =
                pack_bf16x2(fmaxf(acc[ma][na][0] + b0, 0.f), fmaxf(acc[ma][na][1] + b1, 0.f));
            As[kp * 136 + r0 + 8] =
                pack_bf16x2(fmaxf(acc[ma][na][2] + b0, 0.f), fmaxf(acc[ma][na][3] + b1, 0.f));
        }
    }
#pragma unroll
    for (int i = 0; i < 32; ++i) {
        int idx = tid + i * 256;
        int kp = idx >> 7, n = idx & 127;
        Bs[kp * 136 + n] = pack_bf16x2(Wg0[(size_t)(2 * kp) * 128 + n],
                                       Wg0[(size_t)(2 * kp + 1) * 128 + n]);
    }
    __syncthreads();

#pragma unroll
    for (int ma = 0; ma < 2; ++ma)
#pragma unroll
        for (int na = 0; na < 8; ++na)
#pragma unroll
            for (int q = 0; q < 4; ++q) acc[ma][na][q] = 0.f;

#pragma unroll
    for (int ks = 0; ks < 8; ++ks) {
        int kpb = ks * 8;
        uint32_t af[2][4];
#pragma unroll
        for (int ma = 0; ma < 2; ++ma) {
            int rr = wr * 32 + ma * 16 + g;
            af[ma][0] = As[(kpb + t) * 136 + rr];
            af[ma][1] = As[(kpb + t) * 136 + rr + 8];
            af[ma][2] = As[(kpb + t + 4) * 136 + rr];
            af[ma][3] = As[(kpb + t + 4) * 136 + rr + 8];
        }
#pragma unroll
        for (int na = 0; na < 8; ++na) {
            int n = wc * 64 + na * 8 + g;
            uint32_t bf[2];
            bf[0] = Bs[(kpb + t) * 136 + n];
            bf[1] = Bs[(kpb + t + 4) * 136 + n];
#pragma unroll
            for (int ma = 0; ma < 2; ++ma) mma_bf16(acc[ma][na], af[ma], bf);
        }
    }
#pragma unroll
    for (int ma = 0; ma < 2; ++ma) {
        int r0 = rowBase + wr * 32 + ma * 16 + g;
#pragma unroll
        for (int na = 0; na < 8; ++na) {
            unsigned short u0 = pack_e4m3x2(acc[ma][na][0], acc[ma][na][1]);
            unsigned short u1 = pack_e4m3x2(acc[ma][na][2], acc[ma][na][3]);
            uint32_t o0 = __shfl_xor_sync(0xffffffffu, (uint32_t)u0, 1);
            uint32_t o1 = __shfl_xor_sync(0xffffffffu, (uint32_t)u1, 1);
            if ((t & 1) == 0) {
                uint32_t w0 = (uint32_t)u0 | (o0 << 16);
                uint32_t w1 = (uint32_t)u1 | (o1 << 16);
                int colB = wc * 64 + na * 8 + 2 * t;
                if (r0 < nRows)
                    *(uint32_t*)(C + (size_t)r0 * 128 + colB) = w0;
                if (r0 + 8 < nRows)
                    *(uint32_t*)(C + (size_t)(r0 + 8) * 128 + colB) = w1;
            }
        }
    }
}

// ============ bf16 GEMM1: hw1 = fp8(h1 @ W_g1) ============
#define G64_AS 0
#define G64_BS (G64_AS + 64 * 136)
#define G64_WORDS (G64_BS + 64 * 72)

__global__ __launch_bounds__(256) void k_gemm64(
    const __nv_bfloat16* __restrict__ A, const float* __restrict__ W,
    uint8_t* __restrict__ C, int nRows) {
    extern __shared__ uint32_t sm[];
    uint32_t* As = sm + G64_AS;
    uint32_t* Bs = sm + G64_BS;

    int tid = threadIdx.x;
    int lane = tid & 31;
    int wid = tid >> 5;
    int g = lane >> 2, t = lane & 3;
    int wr = wid & 3;
    int wc = wid >> 2;
    int rowBase = blockIdx.x * 128;

    const uint32_t* Aw = (const uint32_t*)(A + (size_t)rowBase * 128);
    int rowsHere = nRows - rowBase; if (rowsHere > 128) rowsHere = 128;
#pragma unroll
    for (int i = 0; i < 32; ++i) {
        int idx = tid + i * 256;
        int rr = idx >> 6;
        int kp = idx & 63;
        uint32_t v = 0;
        if (rr < rowsHere) v = Aw[idx];
        As[kp * 136 + rr] = v;
    }
#pragma unroll
    for (int i = 0; i < 16; ++i) {
        int idx = tid + i * 256;
        int kp = idx >> 6;
        int n = idx & 63;
        Bs[kp * 72 + n] = pack_bf16x2(W[(size_t)(2 * kp) * 64 + n],
                                      W[(size_t)(2 * kp + 1) * 64 + n]);
    }
    __syncthreads();

    float acc[2][4][4];
#pragma unroll
    for (int ma = 0; ma < 2; ++ma)
#pragma unroll
        for (int na = 0; na < 4; ++na)
#pragma unroll
            for (int q = 0; q < 4; ++q) acc[ma][na][q] = 0.f;

#pragma unroll
    for (int ks = 0; ks < 8; ++ks) {
        int kpb = ks * 8;
        uint32_t af[2][4];
#pragma unroll
        for (int ma = 0; ma < 2; ++ma) {
            int rr = wr * 32 + ma * 16 + g;
            af[ma][0] = As[(kpb + t) * 136 + rr];
            af[ma][1] = As[(kpb + t) * 136 + rr + 8];
            af[ma][2] = As[(kpb + t + 4) * 136 + rr];
            af[ma][3] = As[(kpb + t + 4) * 136 + rr + 8];
        }
#pragma unroll
        for (int na = 0; na < 4; ++na) {
            int n = wc * 32 + na * 8 + g;
            uint32_t bf[2];
            bf[0] = Bs[(kpb + t) * 72 + n];
            bf[1] = Bs[(kpb + t + 4) * 72 + n];
#pragma unroll
            for (int ma = 0; ma < 2; ++ma) mma_bf16(acc[ma][na], af[ma], bf);
        }
    }
    // epilogue: fp8 pack, 4B stores from even-t lanes
#pragma unroll
    for (int ma = 0; ma < 2; ++ma) {
        int r0 = rowBase + wr * 32 + ma * 16 + g;
#pragma unroll
        for (int na = 0; na < 4; ++na) {
            unsigned short u0 = pack_e4m3x2(acc[ma][na][0], acc[ma][na][1]);
            unsigned short u1 = pack_e4m3x2(acc[ma][na][2], acc[ma][na][3]);
            uint32_t o0 = __shfl_xor_sync(0xffffffffu, (uint32_t)u0, 1);
            uint32_t o1 = __shfl_xor_sync(0xffffffffu, (uint32_t)u1, 1);
            if ((t & 1) == 0) {
                uint32_t w0 = (uint32_t)u0 | (o0 << 16);
                uint32_t w1 = (uint32_t)u1 | (o1 << 16);
                int colB = wc * 32 + na * 8 + 2 * t;
                if (r0 < nRows)
                    *(uint32_t*)(C + (size_t)r0 * 64 + colB) = w0;
                if (r0 + 8 < nRows)
                    *(uint32_t*)(C + (size_t)(r0 + 8) * 64 + colB) = w1;
            }
        }
    }
}

#define GATHER128(J)                                                          \
    {                                                                         \
        int si = __shfl_sync(0xffffffffu, idx, (J));                          \
        float wv = __shfl_sync(0xffffffffu, dv, (J));                         \
        uint32_t u = __ldg((const uint32_t*)(hw + (size_t)si * 128) + lane);  \
        float4 v = fp8x4_to_float4(u);                                        \
        acc.x += v.x * wv; acc.y += v.y * wv;                                 \
        acc.z += v.z * wv; acc.w += v.w * wv;                                 \
    }

// ================= gather aggregation, D=128 fp8 messages -> h1 (bf16) =================
__global__ void k_agg128(const uint8_t* __restrict__ hw, const float* __restrict__ b,
                         __nv_bfloat16* __restrict__ outh, int nRows) {
    int n = blockIdx.x * (blockDim.x >> 5) + (threadIdx.x >> 5);
    if (n >= nRows) return;
    int lane = threadIdx.x & 31;
    float di = g_dinv[n];
    float4 acc;
    {
        uint32_t u = __ldg((const uint32_t*)(hw + (size_t)n * 128) + lane);
        acc = fp8x4_to_float4(u);
    }
    float s2 = di * di;
    acc.x *= s2; acc.y *= s2; acc.z *= s2; acc.w *= s2;

    int cnt = g_cnt[n];
    const int* colp = g_col + n * PAD;
    for (int j0 = 0; j0 < cnt; j0 += 32) {
        int c = cnt - j0; if (c > 32) c = 32;
        int idx = 0; float dv = 0.f;
        if (lane < c) { idx = __ldg(colp + j0 + lane); dv = g_dinv[idx] * di; }
        int jj = 0;
        for (; jj + 8 <= c; jj += 8) {
            GATHER128(jj + 0) GATHER128(jj + 1) GATHER128(jj + 2) GATHER128(jj + 3)
            GATHER128(jj + 4) GATHER128(jj + 5) GATHER128(jj + 6) GATHER128(jj + 7)
        }
        for (; jj < c; ++jj) { GATHER128(jj) }
    }
    const float4 bb = ((const float4*)b)[lane];
    uint2 o;
    o.x = pack_bf16x2(fmaxf(acc.x + bb.x, 0.f), fmaxf(acc.y + bb.y, 0.f));
    o.y = pack_bf16x2(fmaxf(acc.z + bb.z, 0.f), fmaxf(acc.w + bb.w, 0.f));
    ((uint2*)(outh + (size_t)n * 128))[lane] = o;
}

#define GATHER64(J)                                                           \
    {                                                                         \
        int si = __shfl_sync(0xffffffffu, idx, (J));                          \
        float wv = __shfl_sync(0xffffffffu, dv, (J));                         \
        unsigned short u = __ldg((const unsigned short*)(hw + (size_t)si * 64) + lane); \
        float2 v = fp8x2_to_float2(u);                                        \
        acc.x += v.x * wv; acc.y += v.y * wv;                                 \
    }

// ===== gather aggregation D=64 (fp8 messages) + fused node head =====
__global__ void k_agg64_head(const uint8_t* __restrict__ hw, const float* __restrict__ b,
                             const float* __restrict__ Wsw, const float* __restrict__ Wv,
                             const float* __restrict__ bv, float* __restrict__ out_v,
                             int nRows) {
    int n = blockIdx.x * (blockDim.x >> 5) + (threadIdx.x >> 5);
    if (n >= nRows) return;
    int lane = threadIdx.x & 31;
    float di = g_dinv[n];
    float2 acc;
    {
        unsigned short u = __ldg((const unsigned short*)(hw + (size_t)n * 64) + lane);
        acc = fp8x2_to_float2(u);
    }
    float s2 = di * di;
    acc.x *= s2; acc.y *= s2;

    int cnt = g_cnt[n];
    const int* colp = g_col + n * PAD;
    for (int j0 = 0; j0 < cnt; j0 += 32) {
        int c = cnt - j0; if (c > 32) c = 32;
        int idx = 0; float dv = 0.f;
        if (lane < c) { idx = __ldg(colp + j0 + lane); dv = g_dinv[idx] * di; }
        int jj = 0;
        for (; jj + 8 <= c; jj += 8) {
            GATHER64(jj + 0) GATHER64(jj + 1) GATHER64(jj + 2) GATHER64(jj + 3)
            GATHER64(jj + 4) GATHER64(jj + 5) GATHER64(jj + 6) GATHER64(jj + 7)
        }
        for (; jj < c; ++jj) { GATHER64(jj) }
    }
    int c2 = 2 * lane;
    float a0 = fmaxf(acc.x + b[c2], 0.f);
    float a1 = fmaxf(acc.y + b[c2 + 1], 0.f);

    float pp = a0 * Wsw[c2] + a1 * Wsw[c2 + 1];
    float qq = a0 * Wsw[64 + c2] + a1 * Wsw[64 + c2 + 1];
    float vv = a0 * Wv[c2] + a1 * Wv[c2 + 1];
#pragma unroll
    for (int o = 16; o; o >>= 1) {
        pp += __shfl_xor_sync(0xffffffffu, pp, o);
        qq += __shfl_xor_sync(0xffffffffu, qq, o);
        vv += __shfl_xor_sync(0xffffffffu, vv, o);
    }
    if (lane == 0) {
        g_p[n] = pp;
        g_q[n] = qq;
        float vr = 1.f / (1.f + __expf(-(vv + bv[0])));
        float v = 0.9f + 0.2f * vr;
        float vw = fminf(fmaxf(v * v, 0.81f), 1.21f);
        out_v[n] = sqrtf(vw);
    }
}

// ===== per-edge head, 4 edges/thread =====
__global__ void k_edge(const int* __restrict__ ei, int E,
                       const float* __restrict__ bsw, float* __restrict__ out) {
    int e = (blockIdx.x * blockDim.x + threadIdx.x) * 4;
    if (e >= E) return;
    float bb = __ldg(bsw);
    if (e + 4 <= E) {
        int4 s4 = *(const int4*)(ei + e);
        int4 d4 = *(const int4*)(ei + E + e);
        float4 r;
        {
            float z = __ldg(&g_p[s4.x]) + __ldg(&g_q[d4.x]) + bb;
            r.x = fminf(fmaxf(1.f / (1.f + __expf(-z)), 0.f), 1.f);
        }
        {
            float z = __ldg(&g_p[s4.y]) + __ldg(&g_q[d4.y]) + bb;
            r.y = fminf(fmaxf(1.f / (1.f + __expf(-z)), 0.f), 1.f);
        }
        {
            float z = __ldg(&g_p[s4.z]) + __ldg(&g_q[d4.z]) + bb;
            r.z = fminf(fmaxf(1.f / (1.f + __expf(-z)), 0.f), 1.f);
        }
        {
            float z = __ldg(&g_p[s4.w]) + __ldg(&g_q[d4.w]) + bb;
            r.w = fminf(fmaxf(1.f / (1.f + __expf(-z)), 0.f), 1.f);
        }
        *(float4*)(out + e) = r;
    } else {
        for (; e < E; ++e) {
            float z = __ldg(&g_p[ei[e]]) + __ldg(&g_q[ei[E + e]]) + bb;
            out[e] = fminf(fmaxf(1.f / (1.f + __expf(-z)), 0.f), 1.f);
        }
    }
}

extern "C" void kernel_launch(void* const* d_in, const int* in_sizes, int n_in,
                              void* d_out, int out_size) {
    const float* x     = (const float*)d_in[0];
    const int*   ei    = (const int*)d_in[1];
    const float* W_enc = (const float*)d_in[2];
    const float* b_enc = (const float*)d_in[3];
    const float* W_g0  = (const float*)d_in[4];
    const float* b_g0  = (const float*)d_in[5];
    const float* W_g1  = (const float*)d_in[6];
    const float* b_g1  = (const float*)d_in[7];
    const float* W_sw  = (const float*)d_in[8];
    const float* b_sw  = (const float*)d_in[9];
    const float* W_v   = (const float*)d_in[10];
    const float* b_v   = (const float*)d_in[11];
    float* out = (float*)d_out;

    const int N = in_sizes[0] / 16;
    const int E = in_sizes[1] / 2;

    uint8_t *p_hw0, *p_hw1;
    __nv_bfloat16* p_h1;
    cudaGetSymbolAddress((void**)&p_hw0, g_hw0);
    cudaGetSymbolAddress((void**)&p_h1, g_h1);
    cudaGetSymbolAddress((void**)&p_hw1, g_hw1);

    static cudaStream_t s_side = nullptr;
    static cudaEvent_t s_fork = nullptr, s_join = nullptr;
    if (s_side == nullptr) {
        cudaStreamCreateWithFlags(&s_side, cudaStreamNonBlocking);
        cudaEventCreateWithFlags(&s_fork, cudaEventDisableTiming);
        cudaEventCreateWithFlags(&s_join, cudaEventDisableTiming);
        cudaFuncSetAttribute(k_enc_gemm0, cudaFuncAttributeMaxDynamicSharedMemorySize,
                             EG0_WORDS * 4);
        cudaFuncSetAttribute(k_gemm64, cudaFuncAttributeMaxDynamicSharedMemorySize,
                             G64_WORDS * 4);
    }

    // ---- fork: adjacency build on side stream, encoder+GEMM0 on main ----
    cudaEventRecord(s_fork, 0);
    cudaStreamWaitEvent(s_side, s_fork, 0);

    k_zero<<<(N + 255) / 256, 256, 0, s_side>>>(N);
    k_fill<<<(E + 255) / 256, 256, 0, s_side>>>(ei, E);
    k_dinv<<<(N + 255) / 256, 256, 0, s_side>>>(N);
    cudaEventRecord(s_join, s_side);

    k_enc_gemm0<<<(N + 127) / 128, 256, EG0_WORDS * 4>>>(x, W_enc, b_enc, W_g0, p_hw0, N);

    // ---- join ----
    cudaStreamWaitEvent(0, s_join, 0);

    // ---- layer 0 aggregation (fp8 messages) ----
    k_agg128<<<(N + 7) / 8, 256>>>(p_hw0, b_g0, p_h1, N);

    // ---- layer 1 ----
    k_gemm64<<<(N + 127) / 128, 256, G64_WORDS * 4>>>(p_h1, W_g1, p_hw1, N);
    k_agg64_head<<<(N + 7) / 8, 256>>>(p_hw1, b_g1, W_sw, W_v, b_v, out + E, N);

    // ---- per-edge head ----
    k_edge<<<((E + 3) / 4 + 255) / 256, 256>>>(ei, E, b_sw, out);
}